// round 11
// baseline (speedup 1.0000x reference)
#include <cuda_runtime.h>
#include <math.h>

#define BATCH    64
#define DIN      1024
#define DOUT     1024
#define O4S      (DOUT / 4)          // 256 float4s along o
#define OSPLITS  32                  // o-splits
#define OCH      8                   // float4s per o-split = 128 B = 1 cache line
#define BTILE    8
#define BTILES   (BATCH / BTILE)     // 8  -> grid = 32 x 8 = 256 CTAs
#define IG       32                  // i-groups per CTA (one warp-lane-group each)
#define IPG      (DIN / IG)          // 32 i per group
#define THREADS  256                 // = OCH lanes x IG groups

// Fast softplus: max(v,0) + log1p(exp(-|v|)) with MUFU intrinsics.
__device__ __forceinline__ float softplus_fast(float v) {
    float e = __expf(-fabsf(v));
    return fmaxf(v, 0.0f) + __logf(1.0f + e);
}

// ---------------------------------------------------------------------------
// Single kernel, o-split design: every CTA produces FINISHED outputs.
// grid = (OSPLITS, BTILES). CTA owns 8 batches x 32 o-columns, loops all i.
//   thread = (o4 lane 0..7, i-group 0..31); 8 batch accumulators per thread.
// eps: evict-first streaming, one full 128B line per (b,i) row, coalesced.
// ro/mu: read once per (i,o4)-thread; softplus inline (8M evals chip-wide).
// Epilogue: 32-way i-group reduction in smem (reuses x tile), bias, store.
// No partials in DRAM, no second kernel, no atomics -> deterministic.
// ---------------------------------------------------------------------------
__global__ __launch_bounds__(THREADS) void bayes_kernel(
    const float* __restrict__ x,
    const float* __restrict__ mu,
    const float* __restrict__ ro,
    const float* __restrict__ eps,
    const float* __restrict__ mu_bias,
    const float* __restrict__ ro_bias,
    const float* __restrict__ eps_bias,
    float* __restrict__ out)
{
    const int os    = blockIdx.x;            // 0..31
    const int bt    = blockIdx.y;            // 0..7
    const int b0    = bt * BTILE;
    const int o4l   = threadIdx.x & (OCH - 1);   // 0..7
    const int ig    = threadIdx.x >> 3;          // 0..31
    const int o4g   = os * OCH + o4l;            // global float4 index along o

    // 32 KB shared: first used as x tile [8][1024], then reused as the
    // reduction buffer red[IG][OCH][BTILE] of float4 (also exactly 32 KB).
    __shared__ __align__(16) char s_mem[BTILE * DIN * 4];
    float*  sx  = reinterpret_cast<float*>(s_mem);    // sx[bb*DIN + i]
    float4* red = reinterpret_cast<float4*>(s_mem);   // red[ig*64 + o4l*8 + bb]

    for (int idx = threadIdx.x; idx < BTILE * DIN; idx += THREADS)
        sx[idx] = x[(b0 + (idx >> 10)) * DIN + (idx & (DIN - 1))];
    __syncthreads();

    float4 acc[BTILE];
#pragma unroll
    for (int bb = 0; bb < BTILE; bb++) acc[bb] = make_float4(0.f, 0.f, 0.f, 0.f);

    const float4* ro4  = reinterpret_cast<const float4*>(ro);
    const float4* mu4  = reinterpret_cast<const float4*>(mu);
    const float4* eps4 = reinterpret_cast<const float4*>(eps);

    const int i_lo = ig * IPG;
    int row = i_lo * O4S + o4g;                       // ro/mu float4 index
    int e0  = (b0 * DIN + i_lo) * O4S + o4g;          // eps float4 index (<=16.7M)

#pragma unroll 1
    for (int k = 0; k < IPG; k++) {
        const int i = i_lo + k;
        const float4 r = ro4[row];
        const float4 m = mu4[row];
        float4 sg;
        sg.x = softplus_fast(r.x);
        sg.y = softplus_fast(r.y);
        sg.z = softplus_fast(r.z);
        sg.w = softplus_fast(r.w);
#pragma unroll
        for (int bb = 0; bb < BTILE; bb++) {
            const float  xv = sx[bb * DIN + i];
            const float4 e  = __ldcs(&eps4[e0 + bb * (DIN * O4S)]);
            acc[bb].x = fmaf(xv, fmaf(e.x, sg.x, m.x), acc[bb].x);
            acc[bb].y = fmaf(xv, fmaf(e.y, sg.y, m.y), acc[bb].y);
            acc[bb].z = fmaf(xv, fmaf(e.z, sg.z, m.z), acc[bb].z);
            acc[bb].w = fmaf(xv, fmaf(e.w, sg.w, m.w), acc[bb].w);
        }
        row += O4S;
        e0  += O4S;
    }

    __syncthreads();                // all sx reads done before reusing s_mem
#pragma unroll
    for (int bb = 0; bb < BTILE; bb++)
        red[ig * (OCH * BTILE) + o4l * BTILE + bb] = acc[bb];
    __syncthreads();

    // Reduce 32 i-groups -> 64 outputs (8 b x 8 o4). Threads 0..63, fixed
    // group order => deterministic.
    if (threadIdx.x < BTILE * OCH) {
        const int bb  = threadIdx.x >> 3;     // 0..7
        const int o4r = threadIdx.x & 7;      // 0..7
        float4 sum = make_float4(0.f, 0.f, 0.f, 0.f);
#pragma unroll
        for (int g = 0; g < IG; g++) {
            const float4 p = red[g * (OCH * BTILE) + o4r * BTILE + bb];
            sum.x += p.x; sum.y += p.y; sum.z += p.z; sum.w += p.w;
        }

        const int og = os * OCH + o4r;
        const int g4 = (b0 + bb) * O4S + og;
        const float4 rb = reinterpret_cast<const float4*>(ro_bias)[og];
        const float4 mb = reinterpret_cast<const float4*>(mu_bias)[og];
        const float4 eb = reinterpret_cast<const float4*>(eps_bias)[g4];

        float4 res;
        res.x = sum.x + fmaf(eb.x, softplus_fast(rb.x), mb.x);
        res.y = sum.y + fmaf(eb.y, softplus_fast(rb.y), mb.y);
        res.z = sum.z + fmaf(eb.z, softplus_fast(rb.z), mb.z);
        res.w = sum.w + fmaf(eb.w, softplus_fast(rb.w), mb.w);
        reinterpret_cast<float4*>(out)[g4] = res;
    }
}

// ---------------------------------------------------------------------------
// Launch. Inputs (metadata order): x, mu, ro, mu_bias, ro_bias, eps, eps_bias
// ---------------------------------------------------------------------------
extern "C" void kernel_launch(void* const* d_in, const int* in_sizes, int n_in,
                              void* d_out, int out_size) {
    const float* x        = (const float*)d_in[0];
    const float* mu       = (const float*)d_in[1];
    const float* ro       = (const float*)d_in[2];
    const float* mu_bias  = (const float*)d_in[3];
    const float* ro_bias  = (const float*)d_in[4];
    const float* eps      = (const float*)d_in[5];
    const float* eps_bias = (const float*)d_in[6];
    float* out = (float*)d_out;

    dim3 grid(OSPLITS, BTILES);
    bayes_kernel<<<grid, THREADS>>>(x, mu, ro, eps,
                                    mu_bias, ro_bias, eps_bias, out);
}

// round 14
// speedup vs baseline: 1.5494x; 1.5494x over previous
#include <cuda_runtime.h>
#include <math.h>

#define BATCH    64
#define DIN      1024
#define DOUT     1024
#define O4S      (DOUT / 4)          // 256 float4s along o
#define OSPLITS  32                  // o-splits
#define OCH      8                   // float4s per o-split = 128 B = 1 cache line
#define BTILE    8
#define BTILES   (BATCH / BTILE)     // 8  -> grid = 32 x 8 = 256 CTAs
#define IG       32                  // i-groups per CTA
#define IPG      (DIN / IG)          // 32 i per group
#define THREADS  256                 // = OCH lanes x IG groups

// Fast softplus: max(v,0) + log1p(exp(-|v|)) with MUFU intrinsics.
__device__ __forceinline__ float softplus_fast(float v) {
    float e = __expf(-fabsf(v));
    return fmaxf(v, 0.0f) + __logf(1.0f + e);
}

// ---------------------------------------------------------------------------
// Single kernel, o-split: every CTA produces FINISHED outputs (no partials,
// no second launch). grid = (OSPLITS, BTILES). CTA owns 8 batches x 32
// o-columns, loops all 1024 i. thread = (o4 lane 0..7, i-group 0..31);
// 8 batch accumulators/thread. i-loop unrolled 4x -> ~32 eps loads in
// flight per thread (this was the R11 bug: unroll 1 starved MLP).
// Epilogue: 32-way i-group smem reduction (reuses x tile), bias, store.
// ---------------------------------------------------------------------------
__global__ __launch_bounds__(THREADS) void bayes_kernel(
    const float* __restrict__ x,
    const float* __restrict__ mu,
    const float* __restrict__ ro,
    const float* __restrict__ eps,
    const float* __restrict__ mu_bias,
    const float* __restrict__ ro_bias,
    const float* __restrict__ eps_bias,
    float* __restrict__ out)
{
    const int os  = blockIdx.x;              // 0..31
    const int bt  = blockIdx.y;              // 0..7
    const int b0  = bt * BTILE;
    const int o4l = threadIdx.x & (OCH - 1); // 0..7
    const int ig  = threadIdx.x >> 3;        // 0..31
    const int o4g = os * OCH + o4l;          // global float4 index along o

    // 32 KB shared: x tile [8][1024], later reused as reduction buffer
    // red[IG][OCH][BTILE] of float4 (exactly 32 KB as well).
    __shared__ __align__(16) char s_mem[BTILE * DIN * 4];
    float*  sx  = reinterpret_cast<float*>(s_mem);    // sx[bb*DIN + i]
    float4* red = reinterpret_cast<float4*>(s_mem);   // red[ig*64 + o4l*8 + bb]

    for (int idx = threadIdx.x; idx < BTILE * DIN; idx += THREADS)
        sx[idx] = x[(b0 + (idx >> 10)) * DIN + (idx & (DIN - 1))];
    __syncthreads();

    float4 acc[BTILE];
#pragma unroll
    for (int bb = 0; bb < BTILE; bb++) acc[bb] = make_float4(0.f, 0.f, 0.f, 0.f);

    const float4* ro4  = reinterpret_cast<const float4*>(ro);
    const float4* mu4  = reinterpret_cast<const float4*>(mu);
    const float4* eps4 = reinterpret_cast<const float4*>(eps);

    const int i_lo = ig * IPG;
    int row = i_lo * O4S + o4g;               // ro/mu float4 index
    int e0  = (b0 * DIN + i_lo) * O4S + o4g;  // eps float4 index (<= 16.7M)

#pragma unroll 4
    for (int k = 0; k < IPG; k++) {
        const int i = i_lo + k;
        const float4 r = ro4[row];
        const float4 m = mu4[row];
        float4 sg;
        sg.x = softplus_fast(r.x);
        sg.y = softplus_fast(r.y);
        sg.z = softplus_fast(r.z);
        sg.w = softplus_fast(r.w);
#pragma unroll
        for (int bb = 0; bb < BTILE; bb++) {
            const float  xv = sx[bb * DIN + i];
            const float4 e  = __ldcs(&eps4[e0 + bb * (DIN * O4S)]);
            acc[bb].x = fmaf(xv, fmaf(e.x, sg.x, m.x), acc[bb].x);
            acc[bb].y = fmaf(xv, fmaf(e.y, sg.y, m.y), acc[bb].y);
            acc[bb].z = fmaf(xv, fmaf(e.z, sg.z, m.z), acc[bb].z);
            acc[bb].w = fmaf(xv, fmaf(e.w, sg.w, m.w), acc[bb].w);
        }
        row += O4S;
        e0  += O4S;
    }

    __syncthreads();                // all sx reads done before reusing s_mem
#pragma unroll
    for (int bb = 0; bb < BTILE; bb++)
        red[ig * (OCH * BTILE) + o4l * BTILE + bb] = acc[bb];
    __syncthreads();

    // Reduce 32 i-groups -> 64 outputs (8 b x 8 o4). Threads 0..63, fixed
    // group order => deterministic.
    if (threadIdx.x < BTILE * OCH) {
        const int bb  = threadIdx.x >> 3;     // 0..7
        const int o4r = threadIdx.x & 7;      // 0..7
        float4 sum = make_float4(0.f, 0.f, 0.f, 0.f);
#pragma unroll
        for (int g = 0; g < IG; g++) {
            const float4 p = red[g * (OCH * BTILE) + o4r * BTILE + bb];
            sum.x += p.x; sum.y += p.y; sum.z += p.z; sum.w += p.w;
        }

        const int og = os * OCH + o4r;
        const int g4 = (b0 + bb) * O4S + og;
        const float4 rb = reinterpret_cast<const float4*>(ro_bias)[og];
        const float4 mb = reinterpret_cast<const float4*>(mu_bias)[og];
        const float4 eb = reinterpret_cast<const float4*>(eps_bias)[g4];

        float4 res;
        res.x = sum.x + fmaf(eb.x, softplus_fast(rb.x), mb.x);
        res.y = sum.y + fmaf(eb.y, softplus_fast(rb.y), mb.y);
        res.z = sum.z + fmaf(eb.z, softplus_fast(rb.z), mb.z);
        res.w = sum.w + fmaf(eb.w, softplus_fast(rb.w), mb.w);
        reinterpret_cast<float4*>(out)[g4] = res;
    }
}

// ---------------------------------------------------------------------------
// Launch. Inputs (metadata order): x, mu, ro, mu_bias, ro_bias, eps, eps_bias
// ---------------------------------------------------------------------------
extern "C" void kernel_launch(void* const* d_in, const int* in_sizes, int n_in,
                              void* d_out, int out_size) {
    const float* x        = (const float*)d_in[0];
    const float* mu       = (const float*)d_in[1];
    const float* ro       = (const float*)d_in[2];
    const float* mu_bias  = (const float*)d_in[3];
    const float* ro_bias  = (const float*)d_in[4];
    const float* eps      = (const float*)d_in[5];
    const float* eps_bias = (const float*)d_in[6];
    float* out = (float*)d_out;

    dim3 grid(OSPLITS, BTILES);
    bayes_kernel<<<grid, THREADS>>>(x, mu, ro, eps,
                                    mu_bias, ro_bias, eps_bias, out);
}